// round 15
// baseline (speedup 1.0000x reference)
#include <cuda_runtime.h>
#include <cuda_fp16.h>
#include <cstddef>
#include <cstdint>

// Problem constants
#define BB   16
#define SS   1024
#define DM   256
#define BSN  (BB*SS)             // 16384
#define OUT_ELEMS   (BSN*DM)     // 4,194,304
#define ATTN_ELEMS  (BB*8*SS*SS) // 134,217,728

typedef unsigned long long u64;

__device__ __forceinline__ u64 pk2(float x, float y) {
    u64 r; asm("mov.b64 %0, {%1,%2};" : "=l"(r) : "f"(x), "f"(y)); return r;
}
__device__ __forceinline__ void up2(u64 v, float& x, float& y) {
    asm("mov.b64 {%0,%1}, %2;" : "=f"(x), "=f"(y) : "l"(v));
}
__device__ __forceinline__ void ffma2(u64& d, u64 a, u64 b) {
    asm("fma.rn.f32x2 %0, %1, %2, %0;" : "+l"(d) : "l"(a), "l"(b));
}
__device__ __forceinline__ float to_tf32(float x) {
    float r; asm("cvt.rna.tf32.f32 %0, %1;" : "=f"(r) : "f"(x)); return r;
}
__device__ __forceinline__ void mma_tf32(float* d, float a0, float a1, float a2, float a3,
                                         float b0, float b1) {
    asm("mma.sync.aligned.m16n8k8.row.col.f32.tf32.tf32.f32 "
        "{%0,%1,%2,%3}, {%4,%5,%6,%7}, {%8,%9}, {%0,%1,%2,%3};"
        : "+f"(d[0]), "+f"(d[1]), "+f"(d[2]), "+f"(d[3])
        : "r"(__float_as_uint(a0)), "r"(__float_as_uint(a1)),
          "r"(__float_as_uint(a2)), "r"(__float_as_uint(a3)),
          "r"(__float_as_uint(b0)), "r"(__float_as_uint(b1)));
}
__device__ __forceinline__ void cp16(float* smem, const float* gmem) {
    uint32_t s = (uint32_t)__cvta_generic_to_shared(smem);
    asm volatile("cp.async.cg.shared.global [%0], [%1], 16;" :: "r"(s), "l"(gmem));
}
#define CP_COMMIT() asm volatile("cp.async.commit_group;" ::: "memory")
#define CP_WAIT0()  asm volatile("cp.async.wait_group 0;" ::: "memory")
// evict-first streaming stores
__device__ __forceinline__ void st2cs(float* p, float x, float y) {
    asm volatile("st.global.cs.v2.f32 [%0], {%1,%2};" :: "l"(p), "f"(x), "f"(y) : "memory");
}
__device__ __forceinline__ void sth2cs(__half* p, float x, float y) {
    __half2 h = __floats2half2_rn(x, y);
    uint32_t r = *(uint32_t*)&h;
    asm volatile("st.global.cs.u32 [%0], %1;" :: "l"(p), "r"(r) : "memory");
}
__device__ __forceinline__ float2 ldh2cs(const __half* p) {
    uint32_t r;
    asm volatile("ld.global.cs.u32 %0, [%1];" : "=r"(r) : "l"(p));
    __half2 h = *(__half2*)&r;
    return __half22float2(h);
}

// ---------------- scratch (static device memory; no allocation) -------------
__device__ float  g_Q [BSN*DM];
__device__ float  g_V [BSN*DM];
__device__ float  g_KT[BSN*DM];            // (b, n, s)  tf32-rounded
__device__ float  g_O [BSN*DM];            // concat(o_dist, o_adj)
__device__ float  g_Dsm[(size_t)BB*SS*SS]; // softmax(dist + neg)
__device__ __half g_P [(size_t)ATTN_ELEMS];// unnormalized p = exp(logit+neg), fp16

// ---------------- phase A: 3 projections + dist-softmax, ONE launch ---------
__global__ __launch_bounds__(256, 2)
void fusedA_kernel(const float* __restrict__ q_ori, const float* __restrict__ k_ori,
                   const float* __restrict__ v_ori,
                   const float* __restrict__ Wqd, const float* __restrict__ bqd,
                   const float* __restrict__ Wqa, const float* __restrict__ bqa,
                   const float* __restrict__ Wkd, const float* __restrict__ bkd,
                   const float* __restrict__ Wka, const float* __restrict__ bka,
                   const float* __restrict__ Wvd, const float* __restrict__ bvd,
                   const float* __restrict__ Wva, const float* __restrict__ bva,
                   float* __restrict__ Qo, float* __restrict__ KTo, float* __restrict__ Vo,
                   const float* __restrict__ dist, const float* __restrict__ mask,
                   float* __restrict__ Dsm) {
    __shared__ float As[16][132];
    __shared__ float Ws[16][132];
    const int bid = blockIdx.x;
    const int t = threadIdx.x;

    if (bid >= 768) {
        // ---- dist softmax: one warp per row ----
        const int bid2 = bid - 768;
        const int b = bid2 >> 7;
        const int q = (bid2 & 127) * 8 + (t >> 5);
        const int lane = t & 31;
        const float* drow = dist + ((size_t)b*SS + q)*SS;
        const float* mrow = mask + (size_t)b*SS;
        float e[32];
        float s = 0.f;
        #pragma unroll
        for (int u = 0; u < 8; ++u) {
            int idx = u*128 + lane*4;
            float4 d4 = *(const float4*)(drow + idx);
            float4 m4 = *(const float4*)(mrow + idx);
            e[u*4+0] = __expf(fmaf(m4.x, -1e9f, d4.x));
            e[u*4+1] = __expf(fmaf(m4.y, -1e9f, d4.y));
            e[u*4+2] = __expf(fmaf(m4.z, -1e9f, d4.z));
            e[u*4+3] = __expf(fmaf(m4.w, -1e9f, d4.w));
            s += e[u*4+0] + e[u*4+1] + e[u*4+2] + e[u*4+3];
        }
        #pragma unroll
        for (int off = 16; off; off >>= 1) s += __shfl_xor_sync(0xffffffffu, s, off);
        const float inv = 1.f / s;
        float* orow = Dsm + ((size_t)b*SS + q)*SS;
        #pragma unroll
        for (int u = 0; u < 8; ++u) {
            int idx = u*128 + lane*4;
            float4 o;
            o.x = e[u*4+0]*inv; o.y = e[u*4+1]*inv;
            o.z = e[u*4+2]*inv; o.w = e[u*4+3]*inv;
            *(float4*)(orow + idx) = o;
        }
        return;
    }

    // ---- GEMM CTA ----
    const int which = bid >> 8;
    const int sub = bid & 255;
    const int m0 = (sub & 127) * 128;
    const int half = sub >> 7;
    const int n0 = half * 128;
    const float* A  = (which == 0) ? q_ori : (which == 1) ? k_ori : v_ori;
    const float* W  = (which == 0) ? (half ? Wqa : Wqd)
                    : (which == 1) ? (half ? Wka : Wkd)
                                   : (half ? Wva : Wvd);
    const float* bs = (which == 0) ? (half ? bqa : bqd)
                    : (which == 1) ? (half ? bka : bkd)
                                   : (half ? bva : bvd);

    const int tn = t & 15, tm = t >> 4;

    u64 acc[4][8];
    #pragma unroll
    for (int p = 0; p < 4; ++p)
        #pragma unroll
        for (int j = 0; j < 8; ++j) acc[p][j] = 0ull;

    for (int k0 = 0; k0 < 256; k0 += 16) {
        __syncthreads();
        #pragma unroll
        for (int u = 0; u < 2; ++u) {
            int fi  = t + u*256;
            int row = fi >> 2, c4 = fi & 3;
            float4 v = *(const float4*)(A + (size_t)(m0+row)*256 + k0 + c4*4);
            As[c4*4+0][row] = v.x; As[c4*4+1][row] = v.y;
            As[c4*4+2][row] = v.z; As[c4*4+3][row] = v.w;
        }
        #pragma unroll
        for (int u = 0; u < 2; ++u) {
            int fi = t + u*256;
            int k = fi >> 5, n4 = fi & 31;
            *(float4*)(&Ws[k][n4*4]) =
                *(const float4*)(W + (size_t)(k0+k)*128 + n4*4);   // stride 128
        }
        __syncthreads();
        #pragma unroll
        for (int k = 0; k < 16; ++k) {
            ulonglong2 a01 = *(const ulonglong2*)(&As[k][tm*8]);
            ulonglong2 a23 = *(const ulonglong2*)(&As[k][tm*8 + 4]);
            u64 ap[4] = {a01.x, a01.y, a23.x, a23.y};
            float4 w0 = *(const float4*)(&Ws[k][tn*8]);
            float4 w1 = *(const float4*)(&Ws[k][tn*8 + 4]);
            u64 bd[8];
            bd[0] = pk2(w0.x, w0.x); bd[1] = pk2(w0.y, w0.y);
            bd[2] = pk2(w0.z, w0.z); bd[3] = pk2(w0.w, w0.w);
            bd[4] = pk2(w1.x, w1.x); bd[5] = pk2(w1.y, w1.y);
            bd[6] = pk2(w1.z, w1.z); bd[7] = pk2(w1.w, w1.w);
            #pragma unroll
            for (int p = 0; p < 4; ++p)
                #pragma unroll
                for (int j = 0; j < 8; ++j)
                    ffma2(acc[p][j], ap[p], bd[j]);
        }
    }
    float4 bv0 = *(const float4*)(bs + tn*8);
    float4 bv1 = *(const float4*)(bs + tn*8 + 4);
    float bb[8] = {bv0.x, bv0.y, bv0.z, bv0.w, bv1.x, bv1.y, bv1.z, bv1.w};

    if (which == 1) {
        // ---- K branch: transposed tf32 write -> KT[(b*256 + n)*1024 + s] ----
        const int bt = m0 >> 10;
        const int s0 = m0 & 1023;
        #pragma unroll
        for (int j = 0; j < 8; ++j) {
            int n = n0 + tn*8 + j;
            float va[8];
            #pragma unroll
            for (int p = 0; p < 4; ++p) {
                float l, h;
                up2(acc[p][j], l, h);
                va[p*2]   = to_tf32(l + bb[j]);
                va[p*2+1] = to_tf32(h + bb[j]);
            }
            float* dst = KTo + ((size_t)(bt*256 + n))*SS + s0 + tm*8;
            *(float4*)(dst)     = *(float4*)(va);
            *(float4*)(dst + 4) = *(float4*)(va + 4);
        }
        return;
    }

    float* C = (which == 0) ? Qo : Vo;
    const int doRound = (which == 2);
    #pragma unroll
    for (int p = 0; p < 4; ++p) {
        float lo[8], hi[8];
        #pragma unroll
        for (int j = 0; j < 8; ++j) up2(acc[p][j], lo[j], hi[j]);
        int r0 = m0 + tm*8 + p*2;
        float o[8];
        #pragma unroll
        for (int j = 0; j < 8; ++j) o[j] = lo[j] + bb[j];
        if (doRound) {
            #pragma unroll
            for (int j = 0; j < 8; ++j) o[j] = to_tf32(o[j]);
        }
        *(float4*)(C + (size_t)r0*256 + n0 + tn*8)     = *(float4*)(o);
        *(float4*)(C + (size_t)r0*256 + n0 + tn*8 + 4) = *(float4*)(o + 4);
        #pragma unroll
        for (int j = 0; j < 8; ++j) o[j] = hi[j] + bb[j];
        if (doRound) {
            #pragma unroll
            for (int j = 0; j < 8; ++j) o[j] = to_tf32(o[j]);
        }
        *(float4*)(C + (size_t)(r0+1)*256 + n0 + tn*8)     = *(float4*)(o);
        *(float4*)(C + (size_t)(r0+1)*256 + n0 + tn*8 + 4) = *(float4*)(o + 4);
    }
}

// ---------------- GEMM (O-projection, measured 58us) ------------------------
__global__ __launch_bounds__(256)
void gemm2_kernel(const float* __restrict__ A, const float* __restrict__ W,
                  const float* __restrict__ bias, float* __restrict__ C) {
    __shared__ float As[16][132];
    __shared__ float Ws[16][132];
    const int t  = threadIdx.x;
    const int m0 = blockIdx.x * 128;
    const int n0 = blockIdx.y * 128;
    const int tn = t & 15, tm = t >> 4;

    u64 acc[4][8];
    #pragma unroll
    for (int p = 0; p < 4; ++p)
        #pragma unroll
        for (int j = 0; j < 8; ++j) acc[p][j] = 0ull;

    for (int k0 = 0; k0 < 256; k0 += 16) {
        __syncthreads();
        #pragma unroll
        for (int u = 0; u < 2; ++u) {
            int fi  = t + u*256;
            int row = fi >> 2, c4 = fi & 3;
            float4 v = *(const float4*)(A + (size_t)(m0+row)*256 + k0 + c4*4);
            As[c4*4+0][row] = v.x; As[c4*4+1][row] = v.y;
            As[c4*4+2][row] = v.z; As[c4*4+3][row] = v.w;
        }
        #pragma unroll
        for (int u = 0; u < 2; ++u) {
            int fi = t + u*256;
            int k = fi >> 5, n4 = fi & 31;
            *(float4*)(&Ws[k][n4*4]) =
                *(const float4*)(W + (size_t)(k0+k)*256 + n0 + n4*4);
        }
        __syncthreads();
        #pragma unroll
        for (int k = 0; k < 16; ++k) {
            ulonglong2 a01 = *(const ulonglong2*)(&As[k][tm*8]);
            ulonglong2 a23 = *(const ulonglong2*)(&As[k][tm*8 + 4]);
            u64 ap[4] = {a01.x, a01.y, a23.x, a23.y};
            float4 w0 = *(const float4*)(&Ws[k][tn*8]);
            float4 w1 = *(const float4*)(&Ws[k][tn*8 + 4]);
            u64 bd[8];
            bd[0] = pk2(w0.x, w0.x); bd[1] = pk2(w0.y, w0.y);
            bd[2] = pk2(w0.z, w0.z); bd[3] = pk2(w0.w, w0.w);
            bd[4] = pk2(w1.x, w1.x); bd[5] = pk2(w1.y, w1.y);
            bd[6] = pk2(w1.z, w1.z); bd[7] = pk2(w1.w, w1.w);
            #pragma unroll
            for (int p = 0; p < 4; ++p)
                #pragma unroll
                for (int j = 0; j < 8; ++j)
                    ffma2(acc[p][j], ap[p], bd[j]);
        }
    }
    float4 b0 = *(const float4*)(bias + n0 + tn*8);
    float4 b1 = *(const float4*)(bias + n0 + tn*8 + 4);
    float bb[8] = {b0.x, b0.y, b0.z, b0.w, b1.x, b1.y, b1.z, b1.w};
    #pragma unroll
    for (int p = 0; p < 4; ++p) {
        float lo[8], hi[8];
        #pragma unroll
        for (int j = 0; j < 8; ++j) up2(acc[p][j], lo[j], hi[j]);
        int r0 = m0 + tm*8 + p*2;
        float4 o;
        o.x = lo[0]+bb[0]; o.y = lo[1]+bb[1]; o.z = lo[2]+bb[2]; o.w = lo[3]+bb[3];
        *(float4*)(C + (size_t)r0*256 + n0 + tn*8) = o;
        o.x = lo[4]+bb[4]; o.y = lo[5]+bb[5]; o.z = lo[6]+bb[6]; o.w = lo[7]+bb[7];
        *(float4*)(C + (size_t)r0*256 + n0 + tn*8 + 4) = o;
        o.x = hi[0]+bb[0]; o.y = hi[1]+bb[1]; o.z = hi[2]+bb[2]; o.w = hi[3]+bb[3];
        *(float4*)(C + (size_t)(r0+1)*256 + n0 + tn*8) = o;
        o.x = hi[4]+bb[4]; o.y = hi[5]+bb[5]; o.z = hi[6]+bb[6]; o.w = hi[7]+bb[7];
        *(float4*)(C + (size_t)(r0+1)*256 + n0 + tn*8 + 4) = o;
    }
}

// ---------------- fused attention: 64 q/CTA, two-pass, fp16 p-scratch -------
// Pass 1: QK mma + exp; p stored to g_P (fp16, .cs) + rowsums.
// Pass 2: NO K, NO mma, NO exp — read p, w = p*inv*extra -> attnw + w_tl; PV.
__global__ __launch_bounds__(256, 2)
void attn_kernel(const float* __restrict__ Q, const float* __restrict__ KT,
                 const float* __restrict__ V, const float* __restrict__ mask,
                 const float* __restrict__ extraD, const float* __restrict__ extraA,
                 __half* __restrict__ Pbuf,
                 float* __restrict__ attnw, float* __restrict__ Obuf) {
    extern __shared__ float sm[];
    float* q_sm = sm;              // 2304
    float* k_s0 = sm + 2304;       // 4352 (stride 136)
    float* k_s1 = sm + 6656;       // 4352
    float* v_sm = sm + 11008;      // 5120 (stride 40)
    float* w_tl = sm + 16128;      // 8448 (stride 132; reused as partials 8x544)
    float* msk  = sm + 24576;      // 1024
    float* redu = sm + 25600;      // 192

    const int t    = threadIdx.x;
    const int lane = t & 31, warp = t >> 5;
    const int g = lane >> 2, c = lane & 3;
    const int mq = warp & 3, nh = warp >> 2;
    const int q0 = blockIdx.x * 64;
    const int hg = blockIdx.y;
    const int b  = blockIdx.z;
    const int coloff = hg * 32;
    const float* extra = (hg >= 4) ? extraA : extraD;

    #pragma unroll
    for (int u = 0; u < 8; ++u) {
        int i = t + u*256;
        int r = i >> 5, d = i & 31;
        q_sm[r*36 + d] = to_tf32(Q[(size_t)(b*SS + q0 + r)*256 + coloff + d]);
    }
    #pragma unroll
    for (int u = 0; u < 4; ++u)
        msk[t + u*256] = mask[b*SS + t + u*256] * -1e9f;

    const float* ktb   = KT + ((size_t)b*256 + coloff)*SS;
    const float* vbase = V + (size_t)b*SS*256 + coloff;
    const float scale = 0.17677669529663688f;

    const int rlo = mq*16 + g;
    const int rhi = rlo + 8;

    __half* plo = Pbuf + ((size_t)(b*8 + hg)*SS + q0 + rlo)*SS;
    __half* phi = Pbuf + ((size_t)(b*8 + hg)*SS + q0 + rhi)*SS;

    float* kbuf[2] = {k_s0, k_s1};

    // =================== PASS 1: p + row sums ===================
    #pragma unroll
    for (int u = 0; u < 4; ++u) {
        int fi = t + u*256;
        int kd = fi >> 5, c4 = fi & 31;
        cp16(&k_s0[kd*136 + c4*4], ktb + (size_t)kd*SS + c4*4);
    }
    CP_COMMIT(); CP_WAIT0();
    __syncthreads();

    float s_lo = 0.f, s_hi = 0.f;
    for (int tile = 0; tile < 8; ++tile) {
        const int cur = tile & 1;
        const float* ksm = kbuf[cur];
        if (tile < 7) {
            float* dst = kbuf[cur ^ 1];
            #pragma unroll
            for (int u = 0; u < 4; ++u) {
                int fi = t + u*256;
                int kd = fi >> 5, c4 = fi & 31;
                cp16(&dst[kd*136 + c4*4], ktb + (size_t)kd*SS + (tile+1)*128 + c4*4);
            }
            CP_COMMIT();
        }
        float acc[8][4];
        #pragma unroll
        for (int nt = 0; nt < 8; ++nt)
            #pragma unroll
            for (int j = 0; j < 4; ++j) acc[nt][j] = 0.f;
        #pragma unroll
        for (int ks = 0; ks < 4; ++ks) {
            float a0 = q_sm[rlo*36 + ks*8 + c];
            float a1 = q_sm[rhi*36 + ks*8 + c];
            float a2 = q_sm[rlo*36 + ks*8 + c + 4];
            float a3 = q_sm[rhi*36 + ks*8 + c + 4];
            #pragma unroll
            for (int nt = 0; nt < 8; ++nt) {
                int n0 = nh*64 + nt*8 + g;
                float b0 = ksm[(ks*8 + c)*136 + n0];
                float b1 = ksm[(ks*8 + c + 4)*136 + n0];
                mma_tf32(acc[nt], a0, a1, a2, a3, b0, b1);
            }
        }
        #pragma unroll
        for (int nt = 0; nt < 8; ++nt) {
            int key0 = tile*128 + nh*64 + nt*8 + c*2;
            float n0v = msk[key0], n1v = msk[key0+1];
            float e0 = __expf(fmaf(acc[nt][0], scale, n0v));
            float e1 = __expf(fmaf(acc[nt][1], scale, n1v));
            float e2 = __expf(fmaf(acc[nt][2], scale, n0v));
            float e3 = __expf(fmaf(acc[nt][3], scale, n1v));
            s_lo += e0 + e1;
            s_hi += e2 + e3;
            sth2cs(plo + key0, e0, e1);
            sth2cs(phi + key0, e2, e3);
        }
        if (tile < 7) CP_WAIT0();
        __syncthreads();
    }
    s_lo += __shfl_xor_sync(0xffffffffu, s_lo, 1);
    s_lo += __shfl_xor_sync(0xffffffffu, s_lo, 2);
    s_hi += __shfl_xor_sync(0xffffffffu, s_hi, 1);
    s_hi += __shfl_xor_sync(0xffffffffu, s_hi, 2);
    if (c == 0) {
        redu[nh*64 + rlo] = s_lo;
        redu[nh*64 + rhi] = s_hi;
    }
    __syncthreads();
    if (t < 64) redu[128 + t] = 1.f / (redu[t] + redu[64 + t]);
    __syncthreads();
    const float inv_lo = redu[128 + rlo];
    const float inv_hi = redu[128 + rhi];

    const float* exlo = extra + ((size_t)b*SS + q0 + rlo)*SS;
    const float* exhi = extra + ((size_t)b*SS + q0 + rhi)*SS;
    float* wplo = attnw ? attnw + ((size_t)(b*8 + hg)*SS + q0 + rlo)*SS : (float*)0;
    float* wphi = attnw ? attnw + ((size_t)(b*8 + hg)*SS + q0 + rhi)*SS : (float*)0;

    // =================== PASS 2: weights + PV (p from scratch) ===============
    float oc[4][4];
    #pragma unroll
    for (int nt = 0; nt < 4; ++nt)
        #pragma unroll
        for (int j = 0; j < 4; ++j) oc[nt][j] = 0.f;

    for (int tile = 0; tile < 8; ++tile) {
        #pragma unroll
        for (int u = 0; u < 4; ++u) {
            int fi = t + u*256;
            int kr = fi >> 3, q4 = fi & 7;
            cp16(&v_sm[kr*40 + q4*4], vbase + (size_t)(tile*128 + kr)*256 + q4*4);
        }
        CP_COMMIT();
        #pragma unroll
        for (int nt = 0; nt < 8; ++nt) {
            int lkey = nh*64 + nt*8 + c*2;
            int key0 = tile*128 + lkey;
            float2 pl = ldh2cs(plo + key0);
            float2 ph = ldh2cs(phi + key0);
            float2 elo = *(const float2*)(exlo + key0);
            float2 ehi = *(const float2*)(exhi + key0);
            float w0 = pl.x * inv_lo * elo.x;
            float w1 = pl.y * inv_lo * elo.y;
            float w2 = ph.x * inv_hi * ehi.x;
            float w3 = ph.y * inv_hi * ehi.y;
            if (wplo) {
                st2cs(wplo + key0, w0, w1);
                st2cs(wphi + key0, w2, w3);
            }
            float2 s;
            s.x = to_tf32(w0); s.y = to_tf32(w1);
            *(float2*)(&w_tl[rlo*132 + lkey]) = s;
            s.x = to_tf32(w2); s.y = to_tf32(w3);
            *(float2*)(&w_tl[rhi*132 + lkey]) = s;
        }
        CP_WAIT0();
        __syncthreads();   // v_sm, w_tl ready
        #pragma unroll
        for (int ks = 0; ks < 8; ++ks) {
            int kb = nh*64 + ks*8;
            float a0 = w_tl[rlo*132 + kb + c];
            float a1 = w_tl[rhi*132 + kb + c];
            float a2 = w_tl[rlo*132 + kb + c + 4];
            float a3 = w_tl[rhi*132 + kb + c + 4];
            #pragma unroll
            for (int nt = 0; nt < 4; ++nt) {
                float b0 = v_sm[(kb + c)*40 + nt*8 + g];
                float b1 = v_sm[(kb + c + 4)*40 + nt*8 + g];
                mma_tf32(oc[nt], a0, a1, a2, a3, b0, b1);
            }
        }
        __syncthreads();   // PV done before v_sm/w_tl overwrite next tile
    }

    // ---- cross-half key reduction via smem ----
    #pragma unroll
    for (int nt = 0; nt < 4; ++nt) {
        float2 o;
        o.x = oc[nt][0]; o.y = oc[nt][1];
        *(float2*)(&w_tl[warp*544 + g*34 + nt*8 + c*2]) = o;
        o.x = oc[nt][2]; o.y = oc[nt][3];
        *(float2*)(&w_tl[warp*544 + (g+8)*34 + nt*8 + c*2]) = o;
    }
    __syncthreads();
    #pragma unroll
    for (int u = 0; u < 8; ++u) {
        int slot = t + u*256;
        int r = slot >> 5, d = slot & 31;
        int m4 = r >> 4, r16 = r & 15;
        float s = w_tl[m4*544 + r16*34 + d] + w_tl[(m4+4)*544 + r16*34 + d];
        Obuf[(size_t)(b*SS + q0 + r)*256 + coloff + d] = s;
    }
}

// ---------------- launch --------------------------------------------------
extern "C" void kernel_launch(void* const* d_in, const int* in_sizes, int n_in,
                              void* d_out, int out_size) {
    const float* v_ori = (const float*)d_in[0];
    const float* k_ori = (const float*)d_in[1];
    const float* q_ori = (const float*)d_in[2];
    const float* mask  = (const float*)d_in[3];
    const float* adj   = (const float*)d_in[4];
    const float* dist  = (const float*)d_in[5];
    const float* Wq_d = (const float*)d_in[6];  const float* bq_d = (const float*)d_in[7];
    const float* Wk_d = (const float*)d_in[8];  const float* bk_d = (const float*)d_in[9];
    const float* Wv_d = (const float*)d_in[10]; const float* bv_d = (const float*)d_in[11];
    const float* Wq_a = (const float*)d_in[12]; const float* bq_a = (const float*)d_in[13];
    const float* Wk_a = (const float*)d_in[14]; const float* bk_a = (const float*)d_in[15];
    const float* Wv_a = (const float*)d_in[16]; const float* bv_a = (const float*)d_in[17];
    const float* Wo   = (const float*)d_in[18]; const float* bo   = (const float*)d_in[19];

    float* out   = (float*)d_out;
    float* attnw = (out_size >= OUT_ELEMS + ATTN_ELEMS) ? out + OUT_ELEMS : (float*)0;

    float *pQ,*pV,*pKT,*pO,*pD;
    __half* pP;
    cudaGetSymbolAddress((void**)&pQ,  g_Q);
    cudaGetSymbolAddress((void**)&pV,  g_V);
    cudaGetSymbolAddress((void**)&pKT, g_KT);
    cudaGetSymbolAddress((void**)&pO,  g_O);
    cudaGetSymbolAddress((void**)&pD,  g_Dsm);
    cudaGetSymbolAddress((void**)&pP,  g_P);

    const int ATTN_SMEM = 25792 * 4;   // 103,168 B -> 2 CTAs/SM
    cudaFuncSetAttribute(attn_kernel, cudaFuncAttributeMaxDynamicSharedMemorySize, ATTN_SMEM);

    // #0: fused phase A — 3 projections (K writes KT transposed) + softmax
    fusedA_kernel<<<768 + 2048, 256>>>(
        q_ori, k_ori, v_ori,
        Wq_d, bq_d, Wq_a, bq_a,
        Wk_d, bk_d, Wk_a, bk_a,
        Wv_d, bv_d, Wv_a, bv_a,
        pQ, pKT, pV,
        dist, mask, pD);

    // #1: fused attention (fp16 p-scratch; pass 2 has no K/mma/exp)
    dim3 agrid(16, 8, 16);
    attn_kernel<<<agrid, 256, ATTN_SMEM>>>(pQ, pKT, pV, mask, pD, adj, pP, attnw, pO);

    // #2: output projection
    gemm2_kernel<<<dim3(128, 2), 256>>>(pO, Wo, bo, out);
}

// round 16
// speedup vs baseline: 1.3423x; 1.3423x over previous
#include <cuda_runtime.h>
#include <cstddef>
#include <cstdint>

// Problem constants
#define BB   16
#define SS   1024
#define DM   256
#define BSN  (BB*SS)             // 16384
#define OUT_ELEMS   (BSN*DM)     // 4,194,304
#define ATTN_ELEMS  (BB*8*SS*SS) // 134,217,728

typedef unsigned long long u64;

__device__ __forceinline__ u64 pk2(float x, float y) {
    u64 r; asm("mov.b64 %0, {%1,%2};" : "=l"(r) : "f"(x), "f"(y)); return r;
}
__device__ __forceinline__ void up2(u64 v, float& x, float& y) {
    asm("mov.b64 {%0,%1}, %2;" : "=f"(x), "=f"(y) : "l"(v));
}
__device__ __forceinline__ void ffma2(u64& d, u64 a, u64 b) {
    asm("fma.rn.f32x2 %0, %1, %2, %0;" : "+l"(d) : "l"(a), "l"(b));
}
__device__ __forceinline__ float to_tf32(float x) {
    float r; asm("cvt.rna.tf32.f32 %0, %1;" : "=f"(r) : "f"(x)); return r;
}
__device__ __forceinline__ void mma_tf32(float* d, float a0, float a1, float a2, float a3,
                                         float b0, float b1) {
    asm("mma.sync.aligned.m16n8k8.row.col.f32.tf32.tf32.f32 "
        "{%0,%1,%2,%3}, {%4,%5,%6,%7}, {%8,%9}, {%0,%1,%2,%3};"
        : "+f"(d[0]), "+f"(d[1]), "+f"(d[2]), "+f"(d[3])
        : "r"(__float_as_uint(a0)), "r"(__float_as_uint(a1)),
          "r"(__float_as_uint(a2)), "r"(__float_as_uint(a3)),
          "r"(__float_as_uint(b0)), "r"(__float_as_uint(b1)));
}
__device__ __forceinline__ void cp16(float* smem, const float* gmem) {
    uint32_t s = (uint32_t)__cvta_generic_to_shared(smem);
    asm volatile("cp.async.cg.shared.global [%0], [%1], 16;" :: "r"(s), "l"(gmem));
}
#define CP_COMMIT() asm volatile("cp.async.commit_group;" ::: "memory")
#define CP_WAIT0()  asm volatile("cp.async.wait_group 0;" ::: "memory")
// evict-first streaming store (write-once attn_w; protects L2 working set)
__device__ __forceinline__ void st2cs(float* p, float x, float y) {
    asm volatile("st.global.cs.v2.f32 [%0], {%1,%2};" :: "l"(p), "f"(x), "f"(y) : "memory");
}

// ---------------- scratch (static device memory; no allocation) -------------
__device__ float g_Q [BSN*DM];
__device__ float g_V [BSN*DM];
__device__ float g_KT[BSN*DM];            // (b, n, s)  tf32-rounded
__device__ float g_O [BSN*DM];            // concat(o_dist, o_adj)
__device__ float g_Dsm[(size_t)BB*SS*SS]; // softmax(dist + neg)

// ---------------- phase A: 3 projections + dist-softmax, ONE launch ---------
// bid < 768: GEMM CTA (gemm2 inner loop, unpacked weights).
//   which==0 (Q): row-major fp32 out.
//   which==1 (K): TRANSPOSED tf32 out straight to KT.
//   which==2 (V): row-major tf32-rounded out.
// bid >= 768: dist-softmax, warp-per-row (8 rows per block, 2048 blocks).
__global__ __launch_bounds__(256, 2)
void fusedA_kernel(const float* __restrict__ q_ori, const float* __restrict__ k_ori,
                   const float* __restrict__ v_ori,
                   const float* __restrict__ Wqd, const float* __restrict__ bqd,
                   const float* __restrict__ Wqa, const float* __restrict__ bqa,
                   const float* __restrict__ Wkd, const float* __restrict__ bkd,
                   const float* __restrict__ Wka, const float* __restrict__ bka,
                   const float* __restrict__ Wvd, const float* __restrict__ bvd,
                   const float* __restrict__ Wva, const float* __restrict__ bva,
                   float* __restrict__ Qo, float* __restrict__ KTo, float* __restrict__ Vo,
                   const float* __restrict__ dist, const float* __restrict__ mask,
                   float* __restrict__ Dsm) {
    __shared__ float As[16][132];
    __shared__ float Ws[16][132];
    const int bid = blockIdx.x;
    const int t = threadIdx.x;

    if (bid >= 768) {
        // ---- dist softmax: one warp per row ----
        const int bid2 = bid - 768;                  // 0..2047
        const int b = bid2 >> 7;
        const int q = (bid2 & 127) * 8 + (t >> 5);
        const int lane = t & 31;
        const float* drow = dist + ((size_t)b*SS + q)*SS;
        const float* mrow = mask + (size_t)b*SS;
        float e[32];
        float s = 0.f;
        #pragma unroll
        for (int u = 0; u < 8; ++u) {
            int idx = u*128 + lane*4;
            float4 d4 = *(const float4*)(drow + idx);
            float4 m4 = *(const float4*)(mrow + idx);
            e[u*4+0] = __expf(fmaf(m4.x, -1e9f, d4.x));
            e[u*4+1] = __expf(fmaf(m4.y, -1e9f, d4.y));
            e[u*4+2] = __expf(fmaf(m4.z, -1e9f, d4.z));
            e[u*4+3] = __expf(fmaf(m4.w, -1e9f, d4.w));
            s += e[u*4+0] + e[u*4+1] + e[u*4+2] + e[u*4+3];
        }
        #pragma unroll
        for (int off = 16; off; off >>= 1) s += __shfl_xor_sync(0xffffffffu, s, off);
        const float inv = 1.f / s;
        float* orow = Dsm + ((size_t)b*SS + q)*SS;
        #pragma unroll
        for (int u = 0; u < 8; ++u) {
            int idx = u*128 + lane*4;
            float4 o;
            o.x = e[u*4+0]*inv; o.y = e[u*4+1]*inv;
            o.z = e[u*4+2]*inv; o.w = e[u*4+3]*inv;
            *(float4*)(orow + idx) = o;
        }
        return;
    }

    // ---- GEMM CTA ----
    const int which = bid >> 8;
    const int sub = bid & 255;
    const int m0 = (sub & 127) * 128;
    const int half = sub >> 7;
    const int n0 = half * 128;
    const float* A  = (which == 0) ? q_ori : (which == 1) ? k_ori : v_ori;
    const float* W  = (which == 0) ? (half ? Wqa : Wqd)
                    : (which == 1) ? (half ? Wka : Wkd)
                                   : (half ? Wva : Wvd);
    const float* bs = (which == 0) ? (half ? bqa : bqd)
                    : (which == 1) ? (half ? bka : bkd)
                                   : (half ? bva : bvd);

    const int tn = t & 15, tm = t >> 4;

    u64 acc[4][8];
    #pragma unroll
    for (int p = 0; p < 4; ++p)
        #pragma unroll
        for (int j = 0; j < 8; ++j) acc[p][j] = 0ull;

    for (int k0 = 0; k0 < 256; k0 += 16) {
        __syncthreads();
        #pragma unroll
        for (int u = 0; u < 2; ++u) {
            int fi  = t + u*256;
            int row = fi >> 2, c4 = fi & 3;
            float4 v = *(const float4*)(A + (size_t)(m0+row)*256 + k0 + c4*4);
            As[c4*4+0][row] = v.x; As[c4*4+1][row] = v.y;
            As[c4*4+2][row] = v.z; As[c4*4+3][row] = v.w;
        }
        #pragma unroll
        for (int u = 0; u < 2; ++u) {
            int fi = t + u*256;
            int k = fi >> 5, n4 = fi & 31;
            *(float4*)(&Ws[k][n4*4]) =
                *(const float4*)(W + (size_t)(k0+k)*128 + n4*4);   // stride 128
        }
        __syncthreads();
        #pragma unroll
        for (int k = 0; k < 16; ++k) {
            ulonglong2 a01 = *(const ulonglong2*)(&As[k][tm*8]);
            ulonglong2 a23 = *(const ulonglong2*)(&As[k][tm*8 + 4]);
            u64 ap[4] = {a01.x, a01.y, a23.x, a23.y};
            float4 w0 = *(const float4*)(&Ws[k][tn*8]);
            float4 w1 = *(const float4*)(&Ws[k][tn*8 + 4]);
            u64 bd[8];
            bd[0] = pk2(w0.x, w0.x); bd[1] = pk2(w0.y, w0.y);
            bd[2] = pk2(w0.z, w0.z); bd[3] = pk2(w0.w, w0.w);
            bd[4] = pk2(w1.x, w1.x); bd[5] = pk2(w1.y, w1.y);
            bd[6] = pk2(w1.z, w1.z); bd[7] = pk2(w1.w, w1.w);
            #pragma unroll
            for (int p = 0; p < 4; ++p)
                #pragma unroll
                for (int j = 0; j < 8; ++j)
                    ffma2(acc[p][j], ap[p], bd[j]);
        }
    }
    float4 bv0 = *(const float4*)(bs + tn*8);
    float4 bv1 = *(const float4*)(bs + tn*8 + 4);
    float bb[8] = {bv0.x, bv0.y, bv0.z, bv0.w, bv1.x, bv1.y, bv1.z, bv1.w};

    if (which == 1) {
        // ---- K branch: transposed tf32 write -> KT[(b*256 + n)*1024 + s] ----
        const int bt = m0 >> 10;
        const int s0 = m0 & 1023;
        #pragma unroll
        for (int j = 0; j < 8; ++j) {
            int n = n0 + tn*8 + j;
            float va[8];
            #pragma unroll
            for (int p = 0; p < 4; ++p) {
                float l, h;
                up2(acc[p][j], l, h);
                va[p*2]   = to_tf32(l + bb[j]);
                va[p*2+1] = to_tf32(h + bb[j]);
            }
            float* dst = KTo + ((size_t)(bt*256 + n))*SS + s0 + tm*8;
            *(float4*)(dst)     = *(float4*)(va);
            *(float4*)(dst + 4) = *(float4*)(va + 4);
        }
        return;
    }

    float* C = (which == 0) ? Qo : Vo;
    const int doRound = (which == 2);
    #pragma unroll
    for (int p = 0; p < 4; ++p) {
        float lo[8], hi[8];
        #pragma unroll
        for (int j = 0; j < 8; ++j) up2(acc[p][j], lo[j], hi[j]);
        int r0 = m0 + tm*8 + p*2;
        float o[8];
        #pragma unroll
        for (int j = 0; j < 8; ++j) o[j] = lo[j] + bb[j];
        if (doRound) {
            #pragma unroll
            for (int j = 0; j < 8; ++j) o[j] = to_tf32(o[j]);
        }
        *(float4*)(C + (size_t)r0*256 + n0 + tn*8)     = *(float4*)(o);
        *(float4*)(C + (size_t)r0*256 + n0 + tn*8 + 4) = *(float4*)(o + 4);
        #pragma unroll
        for (int j = 0; j < 8; ++j) o[j] = hi[j] + bb[j];
        if (doRound) {
            #pragma unroll
            for (int j = 0; j < 8; ++j) o[j] = to_tf32(o[j]);
        }
        *(float4*)(C + (size_t)(r0+1)*256 + n0 + tn*8)     = *(float4*)(o);
        *(float4*)(C + (size_t)(r0+1)*256 + n0 + tn*8 + 4) = *(float4*)(o + 4);
    }
}

// ---------------- GEMM (O-projection, measured 58us) ------------------------
__global__ __launch_bounds__(256)
void gemm2_kernel(const float* __restrict__ A, const float* __restrict__ W,
                  const float* __restrict__ bias, float* __restrict__ C) {
    __shared__ float As[16][132];
    __shared__ float Ws[16][132];
    const int t  = threadIdx.x;
    const int m0 = blockIdx.x * 128;
    const int n0 = blockIdx.y * 128;
    const int tn = t & 15, tm = t >> 4;

    u64 acc[4][8];
    #pragma unroll
    for (int p = 0; p < 4; ++p)
        #pragma unroll
        for (int j = 0; j < 8; ++j) acc[p][j] = 0ull;

    for (int k0 = 0; k0 < 256; k0 += 16) {
        __syncthreads();
        #pragma unroll
        for (int u = 0; u < 2; ++u) {
            int fi  = t + u*256;
            int row = fi >> 2, c4 = fi & 3;
            float4 v = *(const float4*)(A + (size_t)(m0+row)*256 + k0 + c4*4);
            As[c4*4+0][row] = v.x; As[c4*4+1][row] = v.y;
            As[c4*4+2][row] = v.z; As[c4*4+3][row] = v.w;
        }
        #pragma unroll
        for (int u = 0; u < 2; ++u) {
            int fi = t + u*256;
            int k = fi >> 5, n4 = fi & 31;
            *(float4*)(&Ws[k][n4*4]) =
                *(const float4*)(W + (size_t)(k0+k)*256 + n0 + n4*4);
        }
        __syncthreads();
        #pragma unroll
        for (int k = 0; k < 16; ++k) {
            ulonglong2 a01 = *(const ulonglong2*)(&As[k][tm*8]);
            ulonglong2 a23 = *(const ulonglong2*)(&As[k][tm*8 + 4]);
            u64 ap[4] = {a01.x, a01.y, a23.x, a23.y};
            float4 w0 = *(const float4*)(&Ws[k][tn*8]);
            float4 w1 = *(const float4*)(&Ws[k][tn*8 + 4]);
            u64 bd[8];
            bd[0] = pk2(w0.x, w0.x); bd[1] = pk2(w0.y, w0.y);
            bd[2] = pk2(w0.z, w0.z); bd[3] = pk2(w0.w, w0.w);
            bd[4] = pk2(w1.x, w1.x); bd[5] = pk2(w1.y, w1.y);
            bd[6] = pk2(w1.z, w1.z); bd[7] = pk2(w1.w, w1.w);
            #pragma unroll
            for (int p = 0; p < 4; ++p)
                #pragma unroll
                for (int j = 0; j < 8; ++j)
                    ffma2(acc[p][j], ap[p], bd[j]);
        }
    }
    float4 b0 = *(const float4*)(bias + n0 + tn*8);
    float4 b1 = *(const float4*)(bias + n0 + tn*8 + 4);
    float bb[8] = {b0.x, b0.y, b0.z, b0.w, b1.x, b1.y, b1.z, b1.w};
    #pragma unroll
    for (int p = 0; p < 4; ++p) {
        float lo[8], hi[8];
        #pragma unroll
        for (int j = 0; j < 8; ++j) up2(acc[p][j], lo[j], hi[j]);
        int r0 = m0 + tm*8 + p*2;
        float4 o;
        o.x = lo[0]+bb[0]; o.y = lo[1]+bb[1]; o.z = lo[2]+bb[2]; o.w = lo[3]+bb[3];
        *(float4*)(C + (size_t)r0*256 + n0 + tn*8) = o;
        o.x = lo[4]+bb[4]; o.y = lo[5]+bb[5]; o.z = lo[6]+bb[6]; o.w = lo[7]+bb[7];
        *(float4*)(C + (size_t)r0*256 + n0 + tn*8 + 4) = o;
        o.x = hi[0]+bb[0]; o.y = hi[1]+bb[1]; o.z = hi[2]+bb[2]; o.w = hi[3]+bb[3];
        *(float4*)(C + (size_t)(r0+1)*256 + n0 + tn*8) = o;
        o.x = hi[4]+bb[4]; o.y = hi[5]+bb[5]; o.z = hi[6]+bb[6]; o.w = hi[7]+bb[7];
        *(float4*)(C + (size_t)(r0+1)*256 + n0 + tn*8 + 4) = o;
    }
}

// ---------------- fused attention: 64 q/CTA, two-pass, cp.async -------------
// Grid: x = head (8), y = q-tile (16), z = batch (16). Consecutive CTAs share
// the SAME extra (Dsm/adj) rows -> one DRAM fetch per row per wave.
__global__ __launch_bounds__(256, 2)
void attn_kernel(const float* __restrict__ Q, const float* __restrict__ KT,
                 const float* __restrict__ V, const float* __restrict__ mask,
                 const float* __restrict__ extraD, const float* __restrict__ extraA,
                 float* __restrict__ attnw, float* __restrict__ Obuf) {
    extern __shared__ float sm[];
    float* q_sm = sm;              // 2304
    float* k_s0 = sm + 2304;       // 4352 (stride 136)
    float* k_s1 = sm + 6656;       // 4352
    float* v_sm = sm + 11008;      // 5120 (stride 40)
    float* w_tl = sm + 16128;      // 8448 (stride 132; reused as partials 8x544)
    float* msk  = sm + 24576;      // 1024
    float* redu = sm + 25600;      // 192

    const int t    = threadIdx.x;
    const int lane = t & 31, warp = t >> 5;
    const int g = lane >> 2, c = lane & 3;
    const int mq = warp & 3, nh = warp >> 2;
    const int hg = blockIdx.x;         // head fastest -> extra-row sharing
    const int q0 = blockIdx.y * 64;
    const int b  = blockIdx.z;
    const int coloff = hg * 32;
    const float* extra = (hg >= 4) ? extraA : extraD;

    #pragma unroll
    for (int u = 0; u < 8; ++u) {
        int i = t + u*256;
        int r = i >> 5, d = i & 31;
        q_sm[r*36 + d] = to_tf32(Q[(size_t)(b*SS + q0 + r)*256 + coloff + d]);
    }
    #pragma unroll
    for (int u = 0; u < 4; ++u)
        msk[t + u*256] = mask[b*SS + t + u*256] * -1e9f;

    const float* ktb   = KT + ((size_t)b*256 + coloff)*SS;
    const float* vbase = V + (size_t)b*SS*256 + coloff;
    const float scale = 0.17677669529663688f;

    const int rlo = mq*16 + g;
    const int rhi = rlo + 8;

    float* kbuf[2] = {k_s0, k_s1};

    // =================== PASS 1: row sums ===================
    #pragma unroll
    for (int u = 0; u < 4; ++u) {
        int fi = t + u*256;
        int kd = fi >> 5, c4 = fi & 31;
        cp16(&k_s0[kd*136 + c4*4], ktb + (size_t)kd*SS + c4*4);
    }
    CP_COMMIT(); CP_WAIT0();
    __syncthreads();

    float s_lo = 0.f, s_hi = 0.f;
    for (int tile = 0; tile < 8; ++tile) {
        const int cur = tile & 1;
        const float* ksm = kbuf[cur];
        if (tile < 7) {
            float* dst = kbuf[cur ^ 1];
            #pragma unroll
            for (int u = 0; u < 4; ++u) {
                int fi = t + u*256;
                int kd = fi >> 5, c4 = fi & 31;
                cp16(&dst[kd*136 + c4*4], ktb + (size_t)kd*SS + (tile+1)*128 + c4*4);
            }
            CP_COMMIT();
        }
        float acc[8][4];
        #pragma unroll
        for (int nt = 0; nt < 8; ++nt)
            #pragma unroll
            for (int j = 0; j < 4; ++j) acc[nt][j] = 0.f;
        #pragma unroll
        for (int ks = 0; ks < 4; ++ks) {
            float a0 = q_sm[rlo*36 + ks*8 + c];
            float a1 = q_sm[rhi*36 + ks*8 + c];
            float a2 = q_sm[rlo*36 + ks*8 + c + 4];
            float a3 = q_sm[rhi*36 + ks*8 + c + 4];
            #pragma unroll
            for (int nt = 0; nt < 8; ++nt) {
                int n0 = nh*64 + nt*8 + g;
                float b0 = ksm[(ks*8 + c)*136 + n0];
                float b1 = ksm[(ks*8 + c + 4)*136 + n0];
                mma_tf32(acc[nt], a0, a1, a2, a3, b0, b1);
            }
        }
        #pragma unroll
        for (int nt = 0; nt < 8; ++nt) {
            int key0 = tile*128 + nh*64 + nt*8 + c*2;
            float n0v = msk[key0], n1v = msk[key0+1];
            s_lo += __expf(fmaf(acc[nt][0], scale, n0v));
            s_lo += __expf(fmaf(acc[nt][1], scale, n1v));
            s_hi += __expf(fmaf(acc[nt][2], scale, n0v));
            s_hi += __expf(fmaf(acc[nt][3], scale, n1v));
        }
        if (tile < 7) CP_WAIT0();
        __syncthreads();
    }
    s_lo += __shfl_xor_sync(0xffffffffu, s_lo, 1);
    s_lo += __shfl_xor_sync(0xffffffffu, s_lo, 2);
    s_hi += __shfl_xor_sync(0xffffffffu, s_hi, 1);
    s_hi += __shfl_xor_sync(0xffffffffu, s_hi, 2);
    if (c == 0) {
        redu[nh*64 + rlo] = s_lo;
        redu[nh*64 + rhi] = s_hi;
    }
    __syncthreads();
    if (t < 64) redu[128 + t] = 1.f / (redu[t] + redu[64 + t]);

    const float* exlo = extra + ((size_t)b*SS + q0 + rlo)*SS;
    const float* exhi = extra + ((size_t)b*SS + q0 + rhi)*SS;
    float* wplo = attnw ? attnw + ((size_t)(b*8 + hg)*SS + q0 + rlo)*SS : (float*)0;
    float* wphi = attnw ? attnw + ((size_t)(b*8 + hg)*SS + q0 + rhi)*SS : (float*)0;

    // =================== PASS 2: weights + PV ===================
    float oc[4][4];
    #pragma unroll
    for (int nt = 0; nt < 4; ++nt)
        #pragma unroll
        for (int j = 0; j < 4; ++j) oc[nt][j] = 0.f;

    #pragma unroll
    for (int u = 0; u < 4; ++u) {
        int fi = t + u*256;
        int kd = fi >> 5, c4 = fi & 31;
        cp16(&k_s0[kd*136 + c4*4], ktb + (size_t)kd*SS + c4*4);
    }
    CP_COMMIT(); CP_WAIT0();
    __syncthreads();                  // redu[128+] and k_s0 visible to all
    const float inv_lo = redu[128 + rlo];
    const float inv_hi = redu[128 + rhi];

    for (int tile = 0; tile < 8; ++tile) {
        const int cur = tile & 1;
        const float* ksm = kbuf[cur];
        #pragma unroll
        for (int u = 0; u < 4; ++u) {
            int fi = t + u*256;
            int kr = fi >> 3, q4 = fi & 7;
            cp16(&v_sm[kr*40 + q4*4], vbase + (size_t)(tile*128 + kr)*256 + q4*4);
        }
        if (tile < 7) {
            float* dst = kbuf[cur ^ 1];
            #pragma unroll
            for (int u = 0; u < 4; ++u) {
                int fi = t + u*256;
                int kd = fi >> 5, c4 = fi & 31;
                cp16(&dst[kd*136 + c4*4], ktb + (size_t)kd*SS + (tile+1)*128 + c4*4);
            }
        }
        CP_COMMIT();
        float acc[8][4];
        #pragma unroll
        for (int nt = 0; nt < 8; ++nt)
            #pragma unroll
            for (int j = 0; j < 4; ++j) acc[nt][j] = 0.f;
        #pragma unroll
        for (int ks = 0; ks < 4; ++ks) {
            float a0 = q_sm[rlo*36 + ks*8 + c];
            float a1 = q_sm[rhi*36 + ks*8 + c];
            float a2 = q_sm[rlo*36 + ks*8 + c + 4];
            float a3 = q_sm[rhi*36 + ks*8 + c + 4];
            #pragma unroll
            for (int nt = 0; nt < 8; ++nt) {
                int n0 = nh*64 + nt*8 + g;
                float b0 = ksm[(ks*8 + c)*136 + n0];
                float b1 = ksm[(ks*8 + c + 4)*136 + n0];
                mma_tf32(acc[nt], a0, a1, a2, a3, b0, b1);
            }
        }
        #pragma unroll
        for (int nt = 0; nt < 8; ++nt) {
            int lkey = nh*64 + nt*8 + c*2;
            int key0 = tile*128 + lkey;
            float n0v = msk[key0], n1v = msk[key0+1];
            float2 elo = *(const float2*)(exlo + key0);
            float2 ehi = *(const float2*)(exhi + key0);
            float w0 = __expf(fmaf(acc[nt][0], scale, n0v)) * inv_lo * elo.x;
            float w1 = __expf(fmaf(acc[nt][1], scale, n1v)) * inv_lo * elo.y;
            float w2 = __expf(fmaf(acc[nt][2], scale, n0v)) * inv_hi * ehi.x;
            float w3 = __expf(fmaf(acc[nt][3], scale, n1v)) * inv_hi * ehi.y;
            if (wplo) {
                st2cs(wplo + key0, w0, w1);
                st2cs(wphi + key0, w2, w3);
            }
            float2 s;
            s.x = to_tf32(w0); s.y = to_tf32(w1);
            *(float2*)(&w_tl[rlo*132 + lkey]) = s;
            s.x = to_tf32(w2); s.y = to_tf32(w3);
            *(float2*)(&w_tl[rhi*132 + lkey]) = s;
        }
        CP_WAIT0();
        __syncthreads();   // v_sm, w_tl, next K ready
        #pragma unroll
        for (int ks = 0; ks < 8; ++ks) {
            int kb = nh*64 + ks*8;
            float a0 = w_tl[rlo*132 + kb + c];
            float a1 = w_tl[rhi*132 + kb + c];
            float a2 = w_tl[rlo*132 + kb + c + 4];
            float a3 = w_tl[rhi*132 + kb + c + 4];
            #pragma unroll
            for (int nt = 0; nt < 4; ++nt) {
                float b0 = v_sm[(kb + c)*40 + nt*8 + g];
                float b1 = v_sm[(kb + c + 4)*40 + nt*8 + g];
                mma_tf32(oc[nt], a0, a1, a2, a3, b0, b1);
            }
        }
        __syncthreads();   // PV done before v_sm/w_tl overwrite next tile
    }

    // ---- cross-half key reduction via smem ----
    #pragma unroll
    for (int nt = 0; nt < 4; ++nt) {
        float2 o;
        o.x = oc[nt][0]; o.y = oc[nt][1];
        *(float2*)(&w_tl[warp*544 + g*34 + nt*8 + c*2]) = o;
        o.x = oc[nt][2]; o.y = oc[nt][3];
        *(float2*)(&w_tl[warp*544 + (g+8)*34 + nt*8 + c*2]) = o;
    }
    __syncthreads();
    #pragma unroll
    for (int u = 0; u < 8; ++u) {
        int slot = t + u*256;
        int r = slot >> 5, d = slot & 31;
        int m4 = r >> 4, r16 = r & 15;
        float s = w_tl[m4*544 + r16*34 + d] + w_tl[(m4+4)*544 + r16*34 + d];
        Obuf[(size_t)(b*SS + q0 + r)*256 + coloff + d] = s;
    }
}

// ---------------- launch --------------------------------------------------
extern "C" void kernel_launch(void* const* d_in, const int* in_sizes, int n_in,
                              void* d_out, int out_size) {
    const float* v_ori = (const float*)d_in[0];
    const float* k_ori = (const float*)d_in[1];
    const float* q_ori = (const float*)d_in[2];
    const float* mask  = (const float*)d_in[3];
    const float* adj   = (const float*)d_in[4];
    const float* dist  = (const float*)d_in[5];
    const float* Wq_d = (const float*)d_in[6];  const float* bq_d = (const float*)d_in[7];
    const float* Wk_d = (const float*)d_in[8];  const float* bk_d = (const float*)d_in[9];
    const float* Wv_d = (const float*)d_in[10]; const float* bv_d = (const float*)d_in[11];
    const float* Wq_a = (const float*)d_in[12]; const float* bq_a = (const float*)d_in[13];
    const float* Wk_a = (const float*)d_in[14]; const float* bk_a = (const float*)d_in[15];
    const float* Wv_a = (const float*)d_in[16]; const float* bv_a = (const float*)d_in[17];
    const float* Wo   = (const float*)d_in[18]; const float* bo   = (const float*)d_in[19];

    float* out   = (float*)d_out;
    float* attnw = (out_size >= OUT_ELEMS + ATTN_ELEMS) ? out + OUT_ELEMS : (float*)0;

    float *pQ,*pV,*pKT,*pO,*pD;
    cudaGetSymbolAddress((void**)&pQ,  g_Q);
    cudaGetSymbolAddress((void**)&pV,  g_V);
    cudaGetSymbolAddress((void**)&pKT, g_KT);
    cudaGetSymbolAddress((void**)&pO,  g_O);
    cudaGetSymbolAddress((void**)&pD,  g_Dsm);

    const int ATTN_SMEM = 25792 * 4;   // 103,168 B -> 2 CTAs/SM
    cudaFuncSetAttribute(attn_kernel, cudaFuncAttributeMaxDynamicSharedMemorySize, ATTN_SMEM);

    // #0: fused phase A — 3 projections (K writes KT transposed) + softmax
    fusedA_kernel<<<768 + 2048, 256>>>(
        q_ori, k_ori, v_ori,
        Wq_d, bq_d, Wq_a, bq_a,
        Wk_d, bk_d, Wk_a, bk_a,
        Wv_d, bv_d, Wv_a, bv_a,
        pQ, pKT, pV,
        dist, mask, pD);

    // #1: fused attention (head-fastest grid for extra-row L2 sharing)
    dim3 agrid(8, 16, 16);
    attn_kernel<<<agrid, 256, ATTN_SMEM>>>(pQ, pKT, pV, mask, pD, adj, attnw, pO);

    // #2: output projection
    gemm2_kernel<<<dim3(128, 2), 256>>>(pO, Wo, bo, out);
}

// round 17
// speedup vs baseline: 1.4179x; 1.0563x over previous
#include <cuda_runtime.h>
#include <cstddef>
#include <cstdint>

// Problem constants
#define BB   16
#define SS   1024
#define DM   256
#define BSN  (BB*SS)             // 16384
#define OUT_ELEMS   (BSN*DM)     // 4,194,304
#define ATTN_ELEMS  (BB*8*SS*SS) // 134,217,728

typedef unsigned long long u64;

__device__ __forceinline__ u64 pk2(float x, float y) {
    u64 r; asm("mov.b64 %0, {%1,%2};" : "=l"(r) : "f"(x), "f"(y)); return r;
}
__device__ __forceinline__ void up2(u64 v, float& x, float& y) {
    asm("mov.b64 {%0,%1}, %2;" : "=f"(x), "=f"(y) : "l"(v));
}
__device__ __forceinline__ void ffma2(u64& d, u64 a, u64 b) {
    asm("fma.rn.f32x2 %0, %1, %2, %0;" : "+l"(d) : "l"(a), "l"(b));
}
__device__ __forceinline__ float to_tf32(float x) {
    float r; asm("cvt.rna.tf32.f32 %0, %1;" : "=f"(r) : "f"(x)); return r;
}
__device__ __forceinline__ void mma_tf32(float* d, float a0, float a1, float a2, float a3,
                                         float b0, float b1) {
    asm("mma.sync.aligned.m16n8k8.row.col.f32.tf32.tf32.f32 "
        "{%0,%1,%2,%3}, {%4,%5,%6,%7}, {%8,%9}, {%0,%1,%2,%3};"
        : "+f"(d[0]), "+f"(d[1]), "+f"(d[2]), "+f"(d[3])
        : "r"(__float_as_uint(a0)), "r"(__float_as_uint(a1)),
          "r"(__float_as_uint(a2)), "r"(__float_as_uint(a3)),
          "r"(__float_as_uint(b0)), "r"(__float_as_uint(b1)));
}
__device__ __forceinline__ void cp16(float* smem, const float* gmem) {
    uint32_t s = (uint32_t)__cvta_generic_to_shared(smem);
    asm volatile("cp.async.cg.shared.global [%0], [%1], 16;" :: "r"(s), "l"(gmem));
}
#define CP_COMMIT() asm volatile("cp.async.commit_group;" ::: "memory")
#define CP_WAIT0()  asm volatile("cp.async.wait_group 0;" ::: "memory")
// evict-first streaming store (write-once attn_w; protects L2 working set)
__device__ __forceinline__ void st2cs(float* p, float x, float y) {
    asm volatile("st.global.cs.v2.f32 [%0], {%1,%2};" :: "l"(p), "f"(x), "f"(y) : "memory");
}

// ---------------- scratch (static device memory; no allocation) -------------
__device__ float g_Q [BSN*DM];
__device__ float g_V [BSN*DM];
__device__ float g_KT[BSN*DM];            // (b, n, s)  tf32-rounded
__device__ float g_O [BSN*DM];            // concat(o_dist, o_adj)
__device__ float g_Dsm[(size_t)BB*SS*SS]; // softmax(dist + neg)

// ---------------- phase A: 3 projections + dist-softmax, ONE launch ---------
__global__ __launch_bounds__(256, 2)
void fusedA_kernel(const float* __restrict__ q_ori, const float* __restrict__ k_ori,
                   const float* __restrict__ v_ori,
                   const float* __restrict__ Wqd, const float* __restrict__ bqd,
                   const float* __restrict__ Wqa, const float* __restrict__ bqa,
                   const float* __restrict__ Wkd, const float* __restrict__ bkd,
                   const float* __restrict__ Wka, const float* __restrict__ bka,
                   const float* __restrict__ Wvd, const float* __restrict__ bvd,
                   const float* __restrict__ Wva, const float* __restrict__ bva,
                   float* __restrict__ Qo, float* __restrict__ KTo, float* __restrict__ Vo,
                   const float* __restrict__ dist, const float* __restrict__ mask,
                   float* __restrict__ Dsm) {
    __shared__ float As[16][132];
    __shared__ float Ws[16][132];
    const int bid = blockIdx.x;
    const int t = threadIdx.x;

    if (bid >= 768) {
        // ---- dist softmax: one warp per row ----
        const int bid2 = bid - 768;                  // 0..2047
        const int b = bid2 >> 7;
        const int q = (bid2 & 127) * 8 + (t >> 5);
        const int lane = t & 31;
        const float* drow = dist + ((size_t)b*SS + q)*SS;
        const float* mrow = mask + (size_t)b*SS;
        float e[32];
        float s = 0.f;
        #pragma unroll
        for (int u = 0; u < 8; ++u) {
            int idx = u*128 + lane*4;
            float4 d4 = *(const float4*)(drow + idx);
            float4 m4 = *(const float4*)(mrow + idx);
            e[u*4+0] = __expf(fmaf(m4.x, -1e9f, d4.x));
            e[u*4+1] = __expf(fmaf(m4.y, -1e9f, d4.y));
            e[u*4+2] = __expf(fmaf(m4.z, -1e9f, d4.z));
            e[u*4+3] = __expf(fmaf(m4.w, -1e9f, d4.w));
            s += e[u*4+0] + e[u*4+1] + e[u*4+2] + e[u*4+3];
        }
        #pragma unroll
        for (int off = 16; off; off >>= 1) s += __shfl_xor_sync(0xffffffffu, s, off);
        const float inv = 1.f / s;
        float* orow = Dsm + ((size_t)b*SS + q)*SS;
        #pragma unroll
        for (int u = 0; u < 8; ++u) {
            int idx = u*128 + lane*4;
            float4 o;
            o.x = e[u*4+0]*inv; o.y = e[u*4+1]*inv;
            o.z = e[u*4+2]*inv; o.w = e[u*4+3]*inv;
            *(float4*)(orow + idx) = o;
        }
        return;
    }

    // ---- GEMM CTA ----
    const int which = bid >> 8;
    const int sub = bid & 255;
    const int m0 = (sub & 127) * 128;
    const int half = sub >> 7;
    const int n0 = half * 128;
    const float* A  = (which == 0) ? q_ori : (which == 1) ? k_ori : v_ori;
    const float* W  = (which == 0) ? (half ? Wqa : Wqd)
                    : (which == 1) ? (half ? Wka : Wkd)
                                   : (half ? Wva : Wvd);
    const float* bs = (which == 0) ? (half ? bqa : bqd)
                    : (which == 1) ? (half ? bka : bkd)
                                   : (half ? bva : bvd);

    const int tn = t & 15, tm = t >> 4;

    u64 acc[4][8];
    #pragma unroll
    for (int p = 0; p < 4; ++p)
        #pragma unroll
        for (int j = 0; j < 8; ++j) acc[p][j] = 0ull;

    for (int k0 = 0; k0 < 256; k0 += 16) {
        __syncthreads();
        #pragma unroll
        for (int u = 0; u < 2; ++u) {
            int fi  = t + u*256;
            int row = fi >> 2, c4 = fi & 3;
            float4 v = *(const float4*)(A + (size_t)(m0+row)*256 + k0 + c4*4);
            As[c4*4+0][row] = v.x; As[c4*4+1][row] = v.y;
            As[c4*4+2][row] = v.z; As[c4*4+3][row] = v.w;
        }
        #pragma unroll
        for (int u = 0; u < 2; ++u) {
            int fi = t + u*256;
            int k = fi >> 5, n4 = fi & 31;
            *(float4*)(&Ws[k][n4*4]) =
                *(const float4*)(W + (size_t)(k0+k)*128 + n4*4);   // stride 128
        }
        __syncthreads();
        #pragma unroll
        for (int k = 0; k < 16; ++k) {
            ulonglong2 a01 = *(const ulonglong2*)(&As[k][tm*8]);
            ulonglong2 a23 = *(const ulonglong2*)(&As[k][tm*8 + 4]);
            u64 ap[4] = {a01.x, a01.y, a23.x, a23.y};
            float4 w0 = *(const float4*)(&Ws[k][tn*8]);
            float4 w1 = *(const float4*)(&Ws[k][tn*8 + 4]);
            u64 bd[8];
            bd[0] = pk2(w0.x, w0.x); bd[1] = pk2(w0.y, w0.y);
            bd[2] = pk2(w0.z, w0.z); bd[3] = pk2(w0.w, w0.w);
            bd[4] = pk2(w1.x, w1.x); bd[5] = pk2(w1.y, w1.y);
            bd[6] = pk2(w1.z, w1.z); bd[7] = pk2(w1.w, w1.w);
            #pragma unroll
            for (int p = 0; p < 4; ++p)
                #pragma unroll
                for (int j = 0; j < 8; ++j)
                    ffma2(acc[p][j], ap[p], bd[j]);
        }
    }
    float4 bv0 = *(const float4*)(bs + tn*8);
    float4 bv1 = *(const float4*)(bs + tn*8 + 4);
    float bb[8] = {bv0.x, bv0.y, bv0.z, bv0.w, bv1.x, bv1.y, bv1.z, bv1.w};

    if (which == 1) {
        // ---- K branch: transposed tf32 write -> KT[(b*256 + n)*1024 + s] ----
        const int bt = m0 >> 10;
        const int s0 = m0 & 1023;
        #pragma unroll
        for (int j = 0; j < 8; ++j) {
            int n = n0 + tn*8 + j;
            float va[8];
            #pragma unroll
            for (int p = 0; p < 4; ++p) {
                float l, h;
                up2(acc[p][j], l, h);
                va[p*2]   = to_tf32(l + bb[j]);
                va[p*2+1] = to_tf32(h + bb[j]);
            }
            float* dst = KTo + ((size_t)(bt*256 + n))*SS + s0 + tm*8;
            *(float4*)(dst)     = *(float4*)(va);
            *(float4*)(dst + 4) = *(float4*)(va + 4);
        }
        return;
    }

    float* C = (which == 0) ? Qo : Vo;
    const int doRound = (which == 2);
    #pragma unroll
    for (int p = 0; p < 4; ++p) {
        float lo[8], hi[8];
        #pragma unroll
        for (int j = 0; j < 8; ++j) up2(acc[p][j], lo[j], hi[j]);
        int r0 = m0 + tm*8 + p*2;
        float o[8];
        #pragma unroll
        for (int j = 0; j < 8; ++j) o[j] = lo[j] + bb[j];
        if (doRound) {
            #pragma unroll
            for (int j = 0; j < 8; ++j) o[j] = to_tf32(o[j]);
        }
        *(float4*)(C + (size_t)r0*256 + n0 + tn*8)     = *(float4*)(o);
        *(float4*)(C + (size_t)r0*256 + n0 + tn*8 + 4) = *(float4*)(o + 4);
        #pragma unroll
        for (int j = 0; j < 8; ++j) o[j] = hi[j] + bb[j];
        if (doRound) {
            #pragma unroll
            for (int j = 0; j < 8; ++j) o[j] = to_tf32(o[j]);
        }
        *(float4*)(C + (size_t)(r0+1)*256 + n0 + tn*8)     = *(float4*)(o);
        *(float4*)(C + (size_t)(r0+1)*256 + n0 + tn*8 + 4) = *(float4*)(o + 4);
    }
}

// ---------------- O-projection: single-term tf32 mma GEMM -------------------
// C[16384x256] = A @ Wo + bo. 128x128 CTA, 8 warps (2x4), warp 64x32, m16n8k8.
// A smem 128x36 (row,k), W smem 32x132 (k,n) — both tf32-rounded, conflict-free.
__global__ __launch_bounds__(256)
void gemmO_kernel(const float* __restrict__ A, const float* __restrict__ W,
                  const float* __restrict__ bias, float* __restrict__ C) {
    __shared__ float Asm[128*36];
    __shared__ float Wsm[32*132];
    const int t    = threadIdx.x;
    const int lane = t & 31, warp = t >> 5;
    const int g = lane >> 2, c = lane & 3;
    const int mw = (warp & 1) * 64, nw = (warp >> 1) * 32;
    const int m0 = blockIdx.x * 128, n0 = blockIdx.y * 128;

    float acc[4][4][4];
    #pragma unroll
    for (int mt = 0; mt < 4; ++mt)
        #pragma unroll
        for (int nt = 0; nt < 4; ++nt)
            #pragma unroll
            for (int j = 0; j < 4; ++j) acc[mt][nt][j] = 0.f;

    for (int k0 = 0; k0 < 256; k0 += 32) {
        __syncthreads();
        #pragma unroll
        for (int u = 0; u < 4; ++u) {      // A tile 128x32
            int fi = t + u*256;
            int row = fi >> 3, c4 = fi & 7;
            float4 v = *(const float4*)(A + (size_t)(m0+row)*256 + k0 + c4*4);
            v.x = to_tf32(v.x); v.y = to_tf32(v.y);
            v.z = to_tf32(v.z); v.w = to_tf32(v.w);
            *(float4*)(&Asm[row*36 + c4*4]) = v;
        }
        #pragma unroll
        for (int u = 0; u < 4; ++u) {      // W tile 32x128
            int fi = t + u*256;
            int kr = fi >> 5, n4 = fi & 31;
            float4 v = *(const float4*)(W + (size_t)(k0+kr)*256 + n0 + n4*4);
            v.x = to_tf32(v.x); v.y = to_tf32(v.y);
            v.z = to_tf32(v.z); v.w = to_tf32(v.w);
            *(float4*)(&Wsm[kr*132 + n4*4]) = v;
        }
        __syncthreads();
        #pragma unroll
        for (int ks = 0; ks < 4; ++ks) {
            float a[4][4];
            #pragma unroll
            for (int mt = 0; mt < 4; ++mt) {
                int r = mw + mt*16 + g;
                a[mt][0] = Asm[r*36 + ks*8 + c];
                a[mt][1] = Asm[(r+8)*36 + ks*8 + c];
                a[mt][2] = Asm[r*36 + ks*8 + c + 4];
                a[mt][3] = Asm[(r+8)*36 + ks*8 + c + 4];
            }
            #pragma unroll
            for (int nt = 0; nt < 4; ++nt) {
                int n = nw + nt*8 + g;
                float b0 = Wsm[(ks*8 + c)*132 + n];
                float b1 = Wsm[(ks*8 + c + 4)*132 + n];
                #pragma unroll
                for (int mt = 0; mt < 4; ++mt)
                    mma_tf32(acc[mt][nt], a[mt][0], a[mt][1], a[mt][2], a[mt][3], b0, b1);
            }
        }
    }

    // epilogue: add bias, write
    #pragma unroll
    for (int nt = 0; nt < 4; ++nt) {
        int col = n0 + nw + nt*8 + c*2;
        float2 bb = *(const float2*)(bias + col);
        #pragma unroll
        for (int mt = 0; mt < 4; ++mt) {
            int r = m0 + mw + mt*16 + g;
            float2 o;
            o.x = acc[mt][nt][0] + bb.x; o.y = acc[mt][nt][1] + bb.y;
            *(float2*)(C + (size_t)r*256 + col) = o;
            o.x = acc[mt][nt][2] + bb.x; o.y = acc[mt][nt][3] + bb.y;
            *(float2*)(C + (size_t)(r+8)*256 + col) = o;
        }
    }
}

// ---------------- fused attention: 64 q/CTA, two-pass, cp.async (R14) -------
__global__ __launch_bounds__(256, 2)
void attn_kernel(const float* __restrict__ Q, const float* __restrict__ KT,
                 const float* __restrict__ V, const float* __restrict__ mask,
                 const float* __restrict__ extraD, const float* __restrict__ extraA,
                 float* __restrict__ attnw, float* __restrict__ Obuf) {
    extern __shared__ float sm[];
    float* q_sm = sm;              // 2304
    float* k_s0 = sm + 2304;       // 4352 (stride 136)
    float* k_s1 = sm + 6656;       // 4352
    float* v_sm = sm + 11008;      // 5120 (stride 40)
    float* w_tl = sm + 16128;      // 8448 (stride 132; reused as partials 8x544)
    float* msk  = sm + 24576;      // 1024
    float* redu = sm + 25600;      // 192

    const int t    = threadIdx.x;
    const int lane = t & 31, warp = t >> 5;
    const int g = lane >> 2, c = lane & 3;
    const int mq = warp & 3, nh = warp >> 2;
    const int q0 = blockIdx.x * 64;
    const int hg = blockIdx.y;
    const int b  = blockIdx.z;
    const int coloff = hg * 32;
    const float* extra = (hg >= 4) ? extraA : extraD;

    #pragma unroll
    for (int u = 0; u < 8; ++u) {
        int i = t + u*256;
        int r = i >> 5, d = i & 31;
        q_sm[r*36 + d] = to_tf32(Q[(size_t)(b*SS + q0 + r)*256 + coloff + d]);
    }
    #pragma unroll
    for (int u = 0; u < 4; ++u)
        msk[t + u*256] = mask[b*SS + t + u*256] * -1e9f;

    const float* ktb   = KT + ((size_t)b*256 + coloff)*SS;
    const float* vbase = V + (size_t)b*SS*256 + coloff;
    const float scale = 0.17677669529663688f;

    const int rlo = mq*16 + g;
    const int rhi = rlo + 8;

    float* kbuf[2] = {k_s0, k_s1};

    // =================== PASS 1: row sums ===================
    #pragma unroll
    for (int u = 0; u < 4; ++u) {
        int fi = t + u*256;
        int kd = fi >> 5, c4 = fi & 31;
        cp16(&k_s0[kd*136 + c4*4], ktb + (size_t)kd*SS + c4*4);
    }
    CP_COMMIT(); CP_WAIT0();
    __syncthreads();

    float s_lo = 0.f, s_hi = 0.f;
    for (int tile = 0; tile < 8; ++tile) {
        const int cur = tile & 1;
        const float* ksm = kbuf[cur];
        if (tile < 7) {
            float* dst = kbuf[cur ^ 1];
            #pragma unroll
            for (int u = 0; u < 4; ++u) {
                int fi = t + u*256;
                int kd = fi >> 5, c4 = fi & 31;
                cp16(&dst[kd*136 + c4*4], ktb + (size_t)kd*SS + (tile+1)*128 + c4*4);
            }
            CP_COMMIT();
        }
        float acc[8][4];
        #pragma unroll
        for (int nt = 0; nt < 8; ++nt)
            #pragma unroll
            for (int j = 0; j < 4; ++j) acc[nt][j] = 0.f;
        #pragma unroll
        for (int ks = 0; ks < 4; ++ks) {
            float a0 = q_sm[rlo*36 + ks*8 + c];
            float a1 = q_sm[rhi*36 + ks*8 + c];
            float a2 = q_sm[rlo*36 + ks*8 + c + 4];
            float a3 = q_sm[rhi*36 + ks*8 + c + 4];
            #pragma unroll
            for (int nt = 0; nt < 8; ++nt) {
                int n0 = nh*64 + nt*8 + g;
                float b0 = ksm[(ks*8 + c)*136 + n0];
                float b1 = ksm[(ks*8 + c + 4)*136 + n0];
                mma_tf32(acc[nt], a0, a1, a2, a3, b0, b1);
            }
        }
        #pragma unroll
        for (int nt = 0; nt < 8; ++nt) {
            int key0 = tile*128 + nh*64 + nt*8 + c*2;
            float n0v = msk[key0], n1v = msk[key0+1];
            s_lo += __expf(fmaf(acc[nt][0], scale, n0v));
            s_lo += __expf(fmaf(acc[nt][1], scale, n1v));
            s_hi += __expf(fmaf(acc[nt][2], scale, n0v));
            s_hi += __expf(fmaf(acc[nt][3], scale, n1v));
        }
        if (tile < 7) CP_WAIT0();
        __syncthreads();
    }
    s_lo += __shfl_xor_sync(0xffffffffu, s_lo, 1);
    s_lo += __shfl_xor_sync(0xffffffffu, s_lo, 2);
    s_hi += __shfl_xor_sync(0xffffffffu, s_hi, 1);
    s_hi += __shfl_xor_sync(0xffffffffu, s_hi, 2);
    if (c == 0) {
        redu[nh*64 + rlo] = s_lo;
        redu[nh*64 + rhi] = s_hi;
    }
    __syncthreads();
    if (t < 64) redu[128 + t] = 1.f / (redu[t] + redu[64 + t]);

    const float* exlo = extra + ((size_t)b*SS + q0 + rlo)*SS;
    const float* exhi = extra + ((size_t)b*SS + q0 + rhi)*SS;
    float* wplo = attnw ? attnw + ((size_t)(b*8 + hg)*SS + q0 + rlo)*SS : (float*)0;
    float* wphi = attnw ? attnw + ((size_t)(b*8 + hg)*SS + q0 + rhi)*SS : (float*)0;

    // =================== PASS 2: weights + PV ===================
    float oc[4][4];
    #pragma unroll
    for (int nt = 0; nt < 4; ++nt)
        #pragma unroll
        for (int j = 0; j < 4; ++j) oc[nt][j] = 0.f;

    #pragma unroll
    for (int u = 0; u < 4; ++u) {
        int fi = t + u*256;
        int kd = fi >> 5, c4 = fi & 31;
        cp16(&k_s0[kd*136 + c4*4], ktb + (size_t)kd*SS + c4*4);
    }
    CP_COMMIT(); CP_WAIT0();
    __syncthreads();                  // redu[128+] and k_s0 visible to all
    const float inv_lo = redu[128 + rlo];
    const float inv_hi = redu[128 + rhi];

    for (int tile = 0; tile < 8; ++tile) {
        const int cur = tile & 1;
        const float* ksm = kbuf[cur];
        #pragma unroll
        for (int u = 0; u < 4; ++u) {
            int fi = t + u*256;
            int kr = fi >> 3, q4 = fi & 7;
            cp16(&v_sm[kr*40 + q4*4], vbase + (size_t)(tile*128 + kr)*256 + q4*4);
        }
        if (tile < 7) {
            float* dst = kbuf[cur ^ 1];
            #pragma unroll
            for (int u = 0; u < 4; ++u) {
                int fi = t + u*256;
                int kd = fi >> 5, c4 = fi & 31;
                cp16(&dst[kd*136 + c4*4], ktb + (size_t)kd*SS + (tile+1)*128 + c4*4);
            }
        }
        CP_COMMIT();
        float acc[8][4];
        #pragma unroll
        for (int nt = 0; nt < 8; ++nt)
            #pragma unroll
            for (int j = 0; j < 4; ++j) acc[nt][j] = 0.f;
        #pragma unroll
        for (int ks = 0; ks < 4; ++ks) {
            float a0 = q_sm[rlo*36 + ks*8 + c];
            float a1 = q_sm[rhi*36 + ks*8 + c];
            float a2 = q_sm[rlo*36 + ks*8 + c + 4];
            float a3 = q_sm[rhi*36 + ks*8 + c + 4];
            #pragma unroll
            for (int nt = 0; nt < 8; ++nt) {
                int n0 = nh*64 + nt*8 + g;
                float b0 = ksm[(ks*8 + c)*136 + n0];
                float b1 = ksm[(ks*8 + c + 4)*136 + n0];
                mma_tf32(acc[nt], a0, a1, a2, a3, b0, b1);
            }
        }
        #pragma unroll
        for (int nt = 0; nt < 8; ++nt) {
            int lkey = nh*64 + nt*8 + c*2;
            int key0 = tile*128 + lkey;
            float n0v = msk[key0], n1v = msk[key0+1];
            float2 elo = *(const float2*)(exlo + key0);
            float2 ehi = *(const float2*)(exhi + key0);
            float w0 = __expf(fmaf(acc[nt][0], scale, n0v)) * inv_lo * elo.x;
            float w1 = __expf(fmaf(acc[nt][1], scale, n1v)) * inv_lo * elo.y;
            float w2 = __expf(fmaf(acc[nt][2], scale, n0v)) * inv_hi * ehi.x;
            float w3 = __expf(fmaf(acc[nt][3], scale, n1v)) * inv_hi * ehi.y;
            if (wplo) {
                st2cs(wplo + key0, w0, w1);
                st2cs(wphi + key0, w2, w3);
            }
            float2 s;
            s.x = to_tf32(w0); s.y = to_tf32(w1);
            *(float2*)(&w_tl[rlo*132 + lkey]) = s;
            s.x = to_tf32(w2); s.y = to_tf32(w3);
            *(float2*)(&w_tl[rhi*132 + lkey]) = s;
        }
        CP_WAIT0();
        __syncthreads();   // v_sm, w_tl, next K ready
        #pragma unroll
        for (int ks = 0; ks < 8; ++ks) {
            int kb = nh*64 + ks*8;
            float a0 = w_tl[rlo*132 + kb + c];
            float a1 = w_tl[rhi*132 + kb + c];
            float a2 = w_tl[rlo*132 + kb + c + 4];
            float a3 = w_tl[rhi*132 + kb + c + 4];
            #pragma unroll
            for (int nt = 0; nt < 4; ++nt) {
                float b0 = v_sm[(kb + c)*40 + nt*8 + g];
                float b1 = v_sm[(kb + c + 4)*40 + nt*8 + g];
                mma_tf32(oc[nt], a0, a1, a2, a3, b0, b1);
            }
        }
        __syncthreads();   // PV done before v_sm/w_tl overwrite next tile
    }

    // ---- cross-half key reduction via smem ----
    #pragma unroll
    for (int nt = 0; nt < 4; ++nt) {
        float2 o;
        o.x = oc[nt][0]; o.y = oc[nt][1];
        *(float2*)(&w_tl[warp*544 + g*34 + nt*8 + c*2]) = o;
        o.x = oc[nt][2]; o.y = oc[nt][3];
        *(float2*)(&w_tl[warp*544 + (g+8)*34 + nt*8 + c*2]) = o;
    }
    __syncthreads();
    #pragma unroll
    for (int u = 0; u < 8; ++u) {
        int slot = t + u*256;
        int r = slot >> 5, d = slot & 31;
        int m4 = r >> 4, r16 = r & 15;
        float s = w_tl[m4*544 + r16*34 + d] + w_tl[(m4+4)*544 + r16*34 + d];
        Obuf[(size_t)(b*SS + q0 + r)*256 + coloff + d] = s;
    }
}

// ---------------- launch --------------------------------------------------
extern "C" void kernel_launch(void* const* d_in, const int* in_sizes, int n_in,
                              void* d_out, int out_size) {
    const float* v_ori = (const float*)d_in[0];
    const float* k_ori = (const float*)d_in[1];
    const float* q_ori = (const float*)d_in[2];
    const float* mask  = (const float*)d_in[3];
    const float* adj   = (const float*)d_in[4];
    const float* dist  = (const float*)d_in[5];
    const float* Wq_d = (const float*)d_in[6];  const float* bq_d = (const float*)d_in[7];
    const float* Wk_d = (const float*)d_in[8];  const float* bk_d = (const float*)d_in[9];
    const float* Wv_d = (const float*)d_in[10]; const float* bv_d = (const float*)d_in[11];
    const float* Wq_a = (const float*)d_in[12]; const float* bq_a = (const float*)d_in[13];
    const float* Wk_a = (const float*)d_in[14]; const float* bk_a = (const float*)d_in[15];
    const float* Wv_a = (const float*)d_in[16]; const float* bv_a = (const float*)d_in[17];
    const float* Wo   = (const float*)d_in[18]; const float* bo   = (const float*)d_in[19];

    float* out   = (float*)d_out;
    float* attnw = (out_size >= OUT_ELEMS + ATTN_ELEMS) ? out + OUT_ELEMS : (float*)0;

    float *pQ,*pV,*pKT,*pO,*pD;
    cudaGetSymbolAddress((void**)&pQ,  g_Q);
    cudaGetSymbolAddress((void**)&pV,  g_V);
    cudaGetSymbolAddress((void**)&pKT, g_KT);
    cudaGetSymbolAddress((void**)&pO,  g_O);
    cudaGetSymbolAddress((void**)&pD,  g_Dsm);

    const int ATTN_SMEM = 25792 * 4;   // 103,168 B -> 2 CTAs/SM
    cudaFuncSetAttribute(attn_kernel, cudaFuncAttributeMaxDynamicSharedMemorySize, ATTN_SMEM);

    // #0: fused phase A — 3 projections (K writes KT transposed) + softmax
    fusedA_kernel<<<768 + 2048, 256>>>(
        q_ori, k_ori, v_ori,
        Wq_d, bq_d, Wq_a, bq_a,
        Wk_d, bk_d, Wk_a, bk_a,
        Wv_d, bv_d, Wv_a, bv_a,
        pQ, pKT, pV,
        dist, mask, pD);

    // #1: fused attention (R14 grid: q-tile fastest)
    dim3 agrid(16, 8, 16);
    attn_kernel<<<agrid, 256, ATTN_SMEM>>>(pQ, pKT, pV, mask, pD, adj, attnw, pO);

    // #2: output projection (single-term tf32 mma)
    gemmO_kernel<<<dim3(128, 2), 256>>>(pO, Wo, bo, out);
}